// round 12
// baseline (speedup 1.0000x reference)
#include <cuda_runtime.h>
#include <cstdint>

// SpatialCorrelationSampler via warp-level mma.sync fp16 m16n8k16 (fp32 acc).
// Round 12: 16x8 tile (halo 24x16 -> L2 traffic x0.8) + fp16 k16 MMA
// (same 10-bit mantissa as the validated tf32 path, 2x MACs/inst).
//
// Per block: M=128 px (16w x 8h), N=384 halo px (24w x 16h), K=256.
// m16 tile mt = image row hy=mt; band = q-rows mt..mt+8, all 3 n8 cols.
// warp = (mt, half): half0 -> band rows 0..4 (15 frags), half1 -> 5..8 (12).

namespace {

constexpr int C = 256, H = 128, W = 128, PATCH = 9, PAD = 4;
constexpr int HW = H * W;
constexpr int TW = 16, TH = 8;
constexpr int HALO_W = 24, HALO_H = 16;
constexpr int CCH = 16, NCHUNK = C / CCH;          // 16
constexpr int CHBYTES = CCH * HW * 4;

constexpr int A_ST = 132;                          // floats (128 + 4), ≡4 mod 16
constexpr int B_ST = 388;                          // floats (384 + 4), ≡4 mod 16
constexpr int A_STAGE = CCH * A_ST * 4;            // 8448
constexpr int B_STAGE = CCH * B_ST * 4;            // 24832
constexpr int STAGE = A_STAGE + B_STAGE;           // 33280
constexpr int STAGES = 4;
constexpr int D_ST = 388;                          // even -> float2 aligned
constexpr int EPI_BYTES = 128 * D_ST * 4;          // 198656
constexpr int DYN_BYTES = EPI_BYTES;               // > STAGES*STAGE (133120)

constexpr int NT = 512;
constexpr int SLOTS = 4;   // (512 A + 1536 B) float4 per chunk / 512 threads

// ---------------- PTX wrappers (baseline ISA) ------------------------------
__device__ __forceinline__ void cp16(uint32_t dst, const void* src, uint32_t sz) {
    asm volatile("cp.async.cg.shared.global [%0], [%1], 16, %2;"
                 :: "r"(dst), "l"(src), "r"(sz));
}
__device__ __forceinline__ void cp_commit() {
    asm volatile("cp.async.commit_group;" ::: "memory");
}
__device__ __forceinline__ void cp_wait2() {
    asm volatile("cp.async.wait_group 2;" ::: "memory");
}
// pack two fp32 -> fp16x2; v_even lands in the LOWER half (validated order)
__device__ __forceinline__ uint32_t pkh(float v_even, float v_odd) {
    uint32_t r;
    asm("cvt.rn.f16x2.f32 %0, %1, %2;" : "=r"(r) : "f"(v_odd), "f"(v_even));
    return r;
}
__device__ __forceinline__ void mma_fp16(float* d, const uint32_t* a,
                                         uint32_t b0, uint32_t b1) {
    asm volatile("mma.sync.aligned.m16n8k16.row.col.f32.f16.f16.f32 "
                 "{%0,%1,%2,%3}, {%4,%5,%6,%7}, {%8,%9}, {%0,%1,%2,%3};"
                 : "+f"(d[0]), "+f"(d[1]), "+f"(d[2]), "+f"(d[3])
                 : "r"(a[0]), "r"(a[1]), "r"(a[2]), "r"(a[3]), "r"(b0), "r"(b1));
}

__global__ __launch_bounds__(NT, 1)
void corr_fp16_kernel(const float* __restrict__ in1,
                      const float* __restrict__ in2,
                      float* __restrict__ out) {
    extern __shared__ char sm[];
    const uint32_t smb = (uint32_t)__cvta_generic_to_shared(sm);

    const int tid  = threadIdx.x;
    const int warp = tid >> 5;
    const int lane = tid & 31;
    const int b  = blockIdx.z;
    const int w0 = blockIdx.x * TW;
    const int h0 = blockIdx.y * TH;

    // ------------- cp.async slot precompute (4 x 16B per thread) -----------
    // slots 0..511: A [k(16)][p(128)];  512..2047: B [k(16)][q(384)]
    uint32_t smoff[SLOTS], gb[SLOTS], sz[SLOTS];
#pragma unroll
    for (int i = 0; i < SLOTS; ++i) {
        int s = tid + i * NT;
        if (s < 512) {                        // A (i = 0)
            int kk = s >> 5, j = s & 31;      // j = p/4
            int hy = j >> 2, wx = (j & 3) * 4;
            smoff[i] = (uint32_t)((kk * A_ST + j * 4) * 4);
            gb[i] = (uint32_t)((((b * C + kk) * H + h0 + hy) * W + w0 + wx) * 4);
            sz[i] = 16;
        } else {                              // B (i = 1..3)
            int u = s - 512;
            int kk = u / 96, j = u % 96;      // j = q/4; q = hy*24+hx
            int hy = j / 6, hx = (j % 6) * 4;
            int gy = h0 + hy - PAD;
            int gx = w0 + hx - PAD;           // 16B aligned: all-in or all-out
            bool ok = (gy >= 0 && gy < H && gx >= 0 && gx + 4 <= W);
            smoff[i] = (uint32_t)(A_STAGE + (kk * B_ST + j * 4) * 4);
            gb[i] = ok ? (uint32_t)((((b * C + kk) * H + gy) * W + gx) * 4) : 0u;
            sz[i] = ok ? 16u : 0u;
        }
    }

    auto issue = [&](int ch) {
        if (ch < NCHUNK) {
            uint32_t sbase = smb + (uint32_t)((ch & 3) * STAGE);
            size_t coff = (size_t)ch * CHBYTES;
#pragma unroll
            for (int i = 0; i < SLOTS; ++i) {
                const char* base = (i == 0) ? (const char*)in1 : (const char*)in2;
                cp16(sbase + smoff[i], base + coff + gb[i], sz[i]);
            }
        }
        cp_commit();   // uniform group accounting (empty groups at the tail)
    };

    issue(0); issue(1); issue(2);

    // ------------- MMA roles: warp = (mt = image row, half) ----------------
    const int g = lane >> 2, t = lane & 3;
    const int mt   = warp >> 1;              // m16 tile: px [mt*16, +16) = row hy=mt
    const int half = warp & 1;
    const int row0 = mt + half * 5;          // first owned q-row
    const int nf   = half ? 12 : 15;         // frags = owned rows * 3 n8 tiles

    float acc[15][4];
#pragma unroll
    for (int j = 0; j < 15; ++j)
#pragma unroll
        for (int q = 0; q < 4; ++q) acc[j][q] = 0.f;

#pragma unroll 1
    for (int k = 0; k < NCHUNK; ++k) {
        cp_wait2();        // exactly 3 groups pending -> group k complete
        __syncthreads();   // stage k visible; stage (k+3)&3 fully read

        issue(k + 3);

        const float* A  = (const float*)(sm + (k & 3) * STAGE);
        const float* Bs = (const float*)(sm + (k & 3) * STAGE + A_STAGE);

        // A fragment (m16 x k16): rows = wx within tile, packed k pairs
        const int p = mt * 16 + g;
        uint32_t a[4];
        a[0] = pkh(A[(2 * t) * A_ST + p],     A[(2 * t + 1) * A_ST + p]);
        a[1] = pkh(A[(2 * t) * A_ST + p + 8], A[(2 * t + 1) * A_ST + p + 8]);
        a[2] = pkh(A[(2 * t + 8) * A_ST + p],     A[(2 * t + 9) * A_ST + p]);
        a[3] = pkh(A[(2 * t + 8) * A_ST + p + 8], A[(2 * t + 9) * A_ST + p + 8]);

#pragma unroll
        for (int j = 0; j < 15; ++j) {
            if (j >= nf) break;
            const int q0 = (row0 + j / 3) * HALO_W + (j % 3) * 8 + g;
            uint32_t b0 = pkh(Bs[(2 * t) * B_ST + q0],
                              Bs[(2 * t + 1) * B_ST + q0]);
            uint32_t b1 = pkh(Bs[(2 * t + 8) * B_ST + q0],
                              Bs[(2 * t + 9) * B_ST + q0]);
            mma_fp16(acc[j], a, b0, b1);
        }
    }

    // ---------------- epilogue: acc -> smem D (banded) -> coalesced stores --
    __syncthreads();            // all MMA smem reads done; stages are dead
    float* D = (float*)sm;      // [px 0..127][q 0..383] stride 388

    {
        const int c2 = t * 2;
        const int px = mt * 16 + g;
#pragma unroll
        for (int j = 0; j < 15; ++j) {
            if (j >= nf) break;
            const int q = (row0 + j / 3) * HALO_W + (j % 3) * 8 + c2;
            *(float2*)&D[px * D_ST + q]       = make_float2(acc[j][0], acc[j][1]);
            *(float2*)&D[(px + 8) * D_ST + q] = make_float2(acc[j][2], acc[j][3]);
        }
    }
    __syncthreads();

    // 648 output rows (81 planes x 8 h-rows) of 16 floats, coalesced
    for (int i = tid; i < TH * PATCH * PATCH; i += NT) {
        const int hp = i & 7, dd = i >> 3;    // dd = dy*9+dx
        const int dy = dd / 9, dx = dd % 9;
        float v[16];
#pragma unroll
        for (int wp = 0; wp < 16; ++wp)
            v[wp] = D[(hp * 16 + wp) * D_ST + (hp + dy) * HALO_W + wp + dx];
        float* op = out + (((size_t)b * (PATCH * PATCH) + dd) * H + (h0 + hp)) * W + w0;
        *(float4*)(op)      = make_float4(v[0],  v[1],  v[2],  v[3]);
        *(float4*)(op + 4)  = make_float4(v[4],  v[5],  v[6],  v[7]);
        *(float4*)(op + 8)  = make_float4(v[8],  v[9],  v[10], v[11]);
        *(float4*)(op + 12) = make_float4(v[12], v[13], v[14], v[15]);
    }
}

}  // namespace

extern "C" void kernel_launch(void* const* d_in, const int* in_sizes, int n_in,
                              void* d_out, int out_size) {
    const float* in1 = (const float*)d_in[0];
    const float* in2 = (const float*)d_in[1];
    float* out = (float*)d_out;

    cudaFuncSetAttribute(corr_fp16_kernel,
                         cudaFuncAttributeMaxDynamicSharedMemorySize,
                         DYN_BYTES);

    int B = in_sizes[0] / (C * H * W);              // 4
    dim3 grid(W / TW, H / TH, B);                   // (8, 16, 4) = 512
    corr_fp16_kernel<<<grid, NT, DYN_BYTES>>>(in1, in2, out);
}

// round 13
// speedup vs baseline: 1.1252x; 1.1252x over previous
#include <cuda_runtime.h>
#include <cstdint>

// SpatialCorrelationSampler via warp-level mma.sync fp16 m16n8k16 (fp32 acc).
// Round 13: round-11 structure (8x8 tile, 256 thr, 2 blocks/SM, band-skip
// GEMM, 4-stage cp.async ring) with the round-12-validated fp16 k16 MMA:
// half the MMA instructions and half the cvts of the tf32 k8 path.
// Strides re-padded (76/268) for conflict-free 2t-row fragment loads.
//
// Per block: tile 8x8 px (M=64), halo 16x16 (N=256), K=256.

namespace {

constexpr int C = 256, H = 128, W = 128, PATCH = 9, PAD = 4;
constexpr int HW = H * W;
constexpr int TW = 8, TH = 8;
constexpr int CCH = 16, NCHUNK = C / CCH;         // 16 chunks, 1 k16 step each
constexpr int CHBYTES = CCH * HW * 4;

// fp32 stage layouts [k][p] / [k][q]; strides 76/268: 2t-row loads hit
// banks 24t+g (all distinct) -> conflict-free fragment loads.
constexpr int A_ST = 76;                          // floats (64 + 12 pad)
constexpr int B_ST = 268;                         // floats (256 + 12 pad)
constexpr int A_STAGE = CCH * A_ST * 4;           // 4864
constexpr int B_STAGE = CCH * B_ST * 4;           // 17152
constexpr int STAGE  = A_STAGE + B_STAGE;         // 22016
constexpr int STAGES = 4;
constexpr int D_STRIDE = 264;                     // even: float2 stores aligned
constexpr int EPI_BYTES = 64 * D_STRIDE * 4;      // 67584
constexpr int DYN_BYTES = STAGES * STAGE;         // 88064 > EPI_BYTES

constexpr int SLOTS = 5;    // (256 A + 1024 B) float4 per chunk / 256 threads

// ---------------- PTX wrappers (baseline ISA) ------------------------------
__device__ __forceinline__ void cp16(uint32_t dst, const void* src, uint32_t sz) {
    asm volatile("cp.async.cg.shared.global [%0], [%1], 16, %2;"
                 :: "r"(dst), "l"(src), "r"(sz));
}
__device__ __forceinline__ void cp_commit() {
    asm volatile("cp.async.commit_group;" ::: "memory");
}
__device__ __forceinline__ void cp_wait2() {
    asm volatile("cp.async.wait_group 2;" ::: "memory");
}
// pack two fp32 -> fp16x2; v_even lands in the LOWER half (round-12 validated)
__device__ __forceinline__ uint32_t pkh(float v_even, float v_odd) {
    uint32_t r;
    asm("cvt.rn.f16x2.f32 %0, %1, %2;" : "=r"(r) : "f"(v_odd), "f"(v_even));
    return r;
}
__device__ __forceinline__ void mma_fp16(float* d, const uint32_t* a,
                                         uint32_t b0, uint32_t b1) {
    asm volatile("mma.sync.aligned.m16n8k16.row.col.f32.f16.f16.f32 "
                 "{%0,%1,%2,%3}, {%4,%5,%6,%7}, {%8,%9}, {%0,%1,%2,%3};"
                 : "+f"(d[0]), "+f"(d[1]), "+f"(d[2]), "+f"(d[3])
                 : "r"(a[0]), "r"(a[1]), "r"(a[2]), "r"(a[3]), "r"(b0), "r"(b1));
}

__global__ __launch_bounds__(256, 2)
void corr_fp16b_kernel(const float* __restrict__ in1,
                       const float* __restrict__ in2,
                       float* __restrict__ out) {
    extern __shared__ char sm[];
    const uint32_t smb = (uint32_t)__cvta_generic_to_shared(sm);

    const int tid  = threadIdx.x;
    const int warp = tid >> 5;
    const int lane = tid & 31;
    const int b  = blockIdx.z;
    const int w0 = blockIdx.x * TW;
    const int h0 = blockIdx.y * TH;

    // ------------- cp.async slot precompute (5 x 16B per thread) -----------
    // slots 0..255: A [k(16)][p(64)];  256..1279: B [k(16)][q(256)]
    uint32_t smoff[SLOTS], gb[SLOTS], sz[SLOTS];
#pragma unroll
    for (int i = 0; i < SLOTS; ++i) {
        int s = tid + i * 256;
        if (s < 256) {                        // A (i = 0)
            int kk = s >> 4, j = s & 15;
            int py = j >> 1, px = (j & 1) * 4;
            smoff[i] = (uint32_t)((kk * A_ST + j * 4) * 4);
            gb[i] = (uint32_t)((((b * C + kk) * H + h0 + py) * W + w0 + px) * 4);
            sz[i] = 16;
        } else {                              // B (i = 1..4)
            int u = s - 256;
            int kk = u >> 6, j = u & 63;
            int hy = j >> 2;
            int gy = h0 + hy - PAD;
            int gx = w0 + (j & 3) * 4 - PAD;  // 16B aligned, all-in or all-out
            bool ok = (gy >= 0 && gy < H && gx >= 0 && gx + 4 <= W);
            smoff[i] = (uint32_t)(A_STAGE + (kk * B_ST + j * 4) * 4);
            gb[i] = ok ? (uint32_t)((((b * C + kk) * H + gy) * W + gx) * 4) : 0u;
            sz[i] = ok ? 16u : 0u;
        }
    }

    auto issue = [&](int ch) {
        if (ch < NCHUNK) {
            uint32_t sbase = smb + (uint32_t)((ch & 3) * STAGE);
            size_t coff = (size_t)ch * CHBYTES;
#pragma unroll
            for (int i = 0; i < SLOTS; ++i) {
                const char* base = (i == 0) ? (const char*)in1 : (const char*)in2;
                cp16(sbase + smoff[i], base + coff + gb[i], sz[i]);
            }
        }
        cp_commit();   // uniform group accounting (empty groups at the tail)
    };

    issue(0); issue(1); issue(2);

    // ------------- MMA roles: warp = (mt, half) ----------------------------
    const int g = lane >> 2, t = lane & 3;
    const int mt   = warp >> 1;            // m16 tile: px [mt*16, +16)
    const int half = warp & 1;
    const int qr0  = 2 * mt + 5 * half;    // first of 5 owned halo rows

    float acc[10][4];                      // j = (row 0..4)*2 + (n8 col 0..1)
#pragma unroll
    for (int j = 0; j < 10; ++j)
#pragma unroll
        for (int q = 0; q < 4; ++q) acc[j][q] = 0.f;

#pragma unroll 1
    for (int k = 0; k < NCHUNK; ++k) {
        cp_wait2();        // exactly 3 groups pending -> group k complete
        __syncthreads();   // stage k visible; stage (k+3)&3 fully read (iter k-1)

        issue(k + 3);

        const float* A  = (const float*)(sm + (k & 3) * STAGE);
        const float* Bs = (const float*)(sm + (k & 3) * STAGE + A_STAGE);

        // A fragment m16 x k16 (round-12 validated map): p = m row, k packed
        const int p = mt * 16 + g;
        uint32_t a[4];
        a[0] = pkh(A[(2 * t) * A_ST + p],         A[(2 * t + 1) * A_ST + p]);
        a[1] = pkh(A[(2 * t) * A_ST + p + 8],     A[(2 * t + 1) * A_ST + p + 8]);
        a[2] = pkh(A[(2 * t + 8) * A_ST + p],     A[(2 * t + 9) * A_ST + p]);
        a[3] = pkh(A[(2 * t + 8) * A_ST + p + 8], A[(2 * t + 9) * A_ST + p + 8]);

#pragma unroll
        for (int j = 0; j < 10; ++j) {
            const int q = (qr0 + (j >> 1)) * 16 + (j & 1) * 8 + g;
            uint32_t b0 = pkh(Bs[(2 * t) * B_ST + q],
                              Bs[(2 * t + 1) * B_ST + q]);
            uint32_t b1 = pkh(Bs[(2 * t + 8) * B_ST + q],
                              Bs[(2 * t + 9) * B_ST + q]);
            mma_fp16(acc[j], a, b0, b1);
        }
    }

    // ---------------- epilogue: acc -> smem D (banded) -> coalesced stores --
    __syncthreads();            // all MMA smem reads done; stages are dead
    float* D = (float*)sm;      // [px 0..63][q 0..255] stride 264

    {
        const int c2 = t * 2;
        const int px = mt * 16 + g;
#pragma unroll
        for (int j = 0; j < 10; ++j) {
            const int q = (qr0 + (j >> 1)) * 16 + (j & 1) * 8 + c2;
            *(float2*)&D[px * D_STRIDE + q]       = make_float2(acc[j][0], acc[j][1]);
            *(float2*)&D[(px + 8) * D_STRIDE + q] = make_float2(acc[j][2], acc[j][3]);
        }
    }
    __syncthreads();

    // 648 output rows (81 planes x 8 h-rows) of 8 floats, coalesced
    for (int i = tid; i < TH * PATCH * PATCH; i += 256) {
        const int hp = i & 7, dd = i >> 3;    // dd = dy*9+dx
        const int dy = dd / 9, dx = dd % 9;
        float v[8];
#pragma unroll
        for (int wp = 0; wp < 8; ++wp)
            v[wp] = D[(hp * 8 + wp) * D_STRIDE + (hp + dy) * 16 + wp + dx];
        float* op = out + (((size_t)b * (PATCH * PATCH) + dd) * H + (h0 + hp)) * W + w0;
        *(float4*)(op)     = make_float4(v[0], v[1], v[2], v[3]);
        *(float4*)(op + 4) = make_float4(v[4], v[5], v[6], v[7]);
    }
}

}  // namespace

extern "C" void kernel_launch(void* const* d_in, const int* in_sizes, int n_in,
                              void* d_out, int out_size) {
    const float* in1 = (const float*)d_in[0];
    const float* in2 = (const float*)d_in[1];
    float* out = (float*)d_out;

    cudaFuncSetAttribute(corr_fp16b_kernel,
                         cudaFuncAttributeMaxDynamicSharedMemorySize,
                         DYN_BYTES);

    int B = in_sizes[0] / (C * H * W);              // 4
    dim3 grid(W / TW, H / TH, B);                   // (16, 16, 4) = 1024
    corr_fp16b_kernel<<<grid, 256, DYN_BYTES>>>(in1, in2, out);
}